// round 8
// baseline (speedup 1.0000x reference)
#include <cuda_runtime.h>
#include <math.h>

// Problem constants (hardcoded in reference)
#define B 32
#define D 128
#define K 512
#define C 10
#define KH 256            // half-K per consumer CTA
#define KQ 128            // quarter-K per producer CTA
#define NT 512
#define NPROD 40          // (c, quarter) producers
#define NCONS 64          // (b, half) consumers

// Cross-CTA state
__device__ float g_fac2[C][K];
__device__ float g_hpart[B][2][C];
__device__ __align__(16) int g_pflag[NPROD];  // producer release-flags
__device__ int g_rowcnt[B];                   // halves done per row
__device__ int g_done = 0;                    // finalizers done (target B)

__device__ __forceinline__ void st_release_gpu(int* p, int v) {
    asm volatile("st.release.gpu.global.s32 [%0], %1;" :: "l"(p), "r"(v) : "memory");
}
__device__ __forceinline__ int4 ld_volatile_v4(const int4* p) {
    int4 v;
    asm volatile("ld.volatile.global.v4.s32 {%0,%1,%2,%3}, [%4];"
                 : "=r"(v.x), "=r"(v.y), "=r"(v.z), "=r"(v.w) : "l"(p) : "memory");
    return v;
}
__device__ __forceinline__ void fence_acq_rel_gpu() {
    asm volatile("fence.acq_rel.gpu;" ::: "memory");
}

// 104 CTAs x 512 threads (single wave on 148 SMs; polling is safe):
//   CTA 0..63   : consumer (b = blk>>1, half = blk&1) — 1024 L1 wavefronts
//   CTA 64..103 : producer (c = pid>>2, q = pid&3)    — 512 wavefronts, early
__global__ __launch_bounds__(NT, 1) void fused_kernel(
    const float* __restrict__ x,
    const float* __restrict__ mu,
    const float* __restrict__ U,
    const float* __restrict__ V,
    float* __restrict__ out) {
    __shared__ float sx[D];
    __shared__ float part[8][KH];    // consumer view: 8 d-groups x 256 (8 KB)
    __shared__ float f1s[KH];
    __shared__ int   sflag;
    // producer view of same 8 KB: 16 d-groups x 128 cols
    float (*part2)[KQ] = reinterpret_cast<float (*)[KQ]>(&part[0][0]);

    const int t    = threadIdx.x;
    const int w    = t >> 5;
    const int lane = t & 31;

    if (blockIdx.x >= NCONS) {
        // ---------------- producer: fac2 row c, quarter q ----------------
        const int pid = blockIdx.x - NCONS;
        const int c   = pid >> 2;
        const int q   = pid & 3;

        if (t < D) sx[t] = mu[c * D + t];

        const int g  = t >> 5;       // d-group 0..15 (8 d-rows each)
        const int tt = t & 31;       // float4 col within quarter (32 x float4)
        const float* Vg = V + q * KQ + g * 8 * K;

        float4 wv[8];
#pragma unroll
        for (int i = 0; i < 8; i++)
            wv[i] = reinterpret_cast<const float4*>(Vg + i * K)[tt];
        __syncthreads();

        float4 acc = make_float4(0.f, 0.f, 0.f, 0.f);
        const float* sg = sx + g * 8;
#pragma unroll
        for (int i = 0; i < 8; i++) {
            const float sv = sg[i];
            acc.x = fmaf(sv, wv[i].x, acc.x);
            acc.y = fmaf(sv, wv[i].y, acc.y);
            acc.z = fmaf(sv, wv[i].z, acc.z);
            acc.w = fmaf(sv, wv[i].w, acc.w);
        }
        reinterpret_cast<float4*>(&part2[g][tt * 4])[0] = acc;
        __syncthreads();

        if (t < 32) {
            float4 r = make_float4(0.f, 0.f, 0.f, 0.f);
#pragma unroll
            for (int gg = 0; gg < 16; gg++) {
                float4 a = reinterpret_cast<const float4*>(&part2[gg][t * 4])[0];
                r.x += a.x; r.y += a.y; r.z += a.z; r.w += a.w;
            }
            reinterpret_cast<float4*>(&g_fac2[c][q * KQ])[t] = r;
        }
        __syncthreads();
        if (t == 0) st_release_gpu(&g_pflag[pid], 1);
        return;
    }

    // ---------------- consumer: row b, half ----------------
    const int row  = blockIdx.x >> 1;
    const int half = blockIdx.x & 1;

    if (t < D) sx[t] = x[row * D + t];

    const int g  = t >> 6;           // d-group 0..7 (16 d-rows each)
    const int tt = t & 63;           // float4 col within half (64 x float4)
    const float* Ug = U + half * KH + g * 16 * K;

    float4 wv[16];                   // front-batched: 16 loads in flight
#pragma unroll
    for (int i = 0; i < 16; i++)
        wv[i] = reinterpret_cast<const float4*>(Ug + i * K)[tt];
    __syncthreads();

    float4 acc = make_float4(0.f, 0.f, 0.f, 0.f);
    const float* sg = sx + g * 16;
#pragma unroll
    for (int i = 0; i < 16; i++) {
        const float sv = sg[i];
        acc.x = fmaf(sv, wv[i].x, acc.x);
        acc.y = fmaf(sv, wv[i].y, acc.y);
        acc.z = fmaf(sv, wv[i].z, acc.z);
        acc.w = fmaf(sv, wv[i].w, acc.w);
    }
    reinterpret_cast<float4*>(&part[g][tt * 4])[0] = acc;

    // flags should already be set (producers are 2x lighter)
    if (t == 0) {
        const int4* fp = reinterpret_cast<const int4*>(g_pflag);
        for (;;) {
            int s = 0;
#pragma unroll
            for (int j = 0; j < NPROD / 4; j++) {
                int4 f = ld_volatile_v4(fp + j);
                s += f.x + f.y + f.z + f.w;
            }
            if (s == NPROD) break;
        }
        fence_acq_rel_gpu();
    }
    __syncthreads();   // part[] ready AND fac2 visible

    // fold d-group partials
    if (t < KH) {
        float f = part[0][t];
#pragma unroll
        for (int gg = 1; gg < 8; gg++) f += part[gg][t];
        f1s[t] = f;
    }
    __syncthreads();

    // one warp per class: dot(f1s, fac2[c, half]) over 256 (2 float4/lane)
    if (w < C) {
        const float4* fa = reinterpret_cast<const float4*>(f1s);
        const float4* fb = reinterpret_cast<const float4*>(&g_fac2[w][half * KH]);
        float p = 0.f;
#pragma unroll
        for (int j = 0; j < 2; j++) {
            const int i4 = lane + j * 32;
            float4 a = fa[i4];
            float4 b2 = fb[i4];
            p += a.x * b2.x + a.y * b2.y + a.z * b2.z + a.w * b2.w;
        }
#pragma unroll
        for (int o = 16; o > 0; o >>= 1)
            p += __shfl_xor_sync(0xffffffffu, p, o);
        if (lane == 0) g_hpart[row][half][w] = p;
    }
    __syncthreads();                  // all hpart stores issued
    if (t == 0) {
        __threadfence();              // release hpart before counter
        sflag = (atomicAdd(&g_rowcnt[row], 1) == 1);
    }
    __syncthreads();
    if (!sflag) return;

    // ---- finale (exactly one CTA per row; fixed-order sum = deterministic)
    if (t == 0) {
        __threadfence();              // acquire partner's hpart
        float h[C];
        float m = -INFINITY;
#pragma unroll
        for (int c = 0; c < C; c++) {
            h[c] = g_hpart[row][0][c] + g_hpart[row][1][c];
            m = fmaxf(m, h[c]);
        }
        float se = 0.f;
#pragma unroll
        for (int c = 0; c < C; c++) se += expf(h[c] - m);
        const float lse = m + logf(se);
#pragma unroll
        for (int c = 0; c < C; c++) out[row * C + c] = h[c] - lse;

        // last finalizer resets all state for the next graph replay
        if (atomicAdd(&g_done, 1) == B - 1) {
#pragma unroll
            for (int j = 0; j < B; j++) g_rowcnt[j] = 0;
#pragma unroll
            for (int j = 0; j < NPROD; j++) g_pflag[j] = 0;
            g_done = 0;
        }
    }
}

extern "C" void kernel_launch(void* const* d_in, const int* in_sizes, int n_in,
                              void* d_out, int out_size) {
    const float* x  = (const float*)d_in[0];  // [32, 128]
    const float* mu = (const float*)d_in[1];  // [10, 128]
    const float* U  = (const float*)d_in[2];  // [128, 512]
    const float* V  = (const float*)d_in[3];  // [128, 512]
    float* out = (float*)d_out;               // [32, 10]

    fused_kernel<<<NCONS + NPROD, NT>>>(x, mu, U, V, out);
}

// round 9
// speedup vs baseline: 1.2149x; 1.2149x over previous
#include <cuda_runtime.h>
#include <math.h>

// Problem constants (hardcoded in reference)
#define B 32
#define D 128
#define K 512
#define C 10
#define NT 1024
#define NFLAGPAD 12       // 10 flags padded to 12 for v4 polling

// Cross-CTA state
__device__ float g_fac2[C][K];
__device__ __align__(16) int g_pflag[NFLAGPAD];  // [10] used, [10..11] always 0
__device__ int g_done = 0;                        // consumers done (target B)

__device__ __forceinline__ void st_release_gpu(int* p, int v) {
    asm volatile("st.release.gpu.global.s32 [%0], %1;" :: "l"(p), "r"(v) : "memory");
}
__device__ __forceinline__ int4 ld_volatile_v4(const int4* p) {
    int4 v;
    asm volatile("ld.volatile.global.v4.s32 {%0,%1,%2,%3}, [%4];"
                 : "=r"(v.x), "=r"(v.y), "=r"(v.z), "=r"(v.w) : "l"(p) : "memory");
    return v;
}
__device__ __forceinline__ void fence_acq_rel_gpu() {
    asm volatile("fence.acq_rel.gpu;" ::: "memory");
}

// 42 CTAs x 1024 threads (one CTA per SM, single wave):
//   CTA 0..31  : consumer b — fac1 row in smem partials, poll flags,
//                warp-per-class dot, parallel softmax, write out[b].
//   CTA 32..41 : producer c — fac2 row, publish slice + release flag.
__global__ __launch_bounds__(NT, 1) void fused_kernel(
    const float* __restrict__ x,
    const float* __restrict__ mu,
    const float* __restrict__ U,
    const float* __restrict__ V,
    float* __restrict__ out) {
    __shared__ float sx[D];
    __shared__ float part[8][K];     // 8 d-groups x 512 (16 KB)
    __shared__ float f1s[K];
    __shared__ float hrow[C];

    const int t    = threadIdx.x;
    const int w    = t >> 5;
    const int lane = t & 31;
    const int g    = t >> 7;         // d-group 0..7 (16 d-rows each)
    const int tt   = t & 127;        // float4 col, full K

    const bool producer = (blockIdx.x >= B);
    const int  row = producer ? (blockIdx.x - B) : blockIdx.x;
    const float* src = producer ? (mu + row * D) : (x + row * D);
    const float* Wg  = (producer ? V : U) + g * 16 * K;

    if (t < D) sx[t] = src[t];

    // front-batched: all 16 LDG.128 in flight before the smem-operand wait
    float4 wv[16];
#pragma unroll
    for (int i = 0; i < 16; i++)
        wv[i] = reinterpret_cast<const float4*>(Wg + i * K)[tt];
    __syncthreads();

    float4 acc = make_float4(0.f, 0.f, 0.f, 0.f);
    const float* sg = sx + g * 16;
#pragma unroll
    for (int i = 0; i < 16; i++) {
        const float sv = sg[i];
        acc.x = fmaf(sv, wv[i].x, acc.x);
        acc.y = fmaf(sv, wv[i].y, acc.y);
        acc.z = fmaf(sv, wv[i].z, acc.z);
        acc.w = fmaf(sv, wv[i].w, acc.w);
    }
    reinterpret_cast<float4*>(&part[g][tt * 4])[0] = acc;
    __syncthreads();

    if (producer) {
        // reduce 8 d-partials, publish fac2 row, release own flag
        if (t < 128) {
            float4 r = make_float4(0.f, 0.f, 0.f, 0.f);
#pragma unroll
            for (int gg = 0; gg < 8; gg++) {
                float4 a = reinterpret_cast<const float4*>(&part[gg][t * 4])[0];
                r.x += a.x; r.y += a.y; r.z += a.z; r.w += a.w;
            }
            reinterpret_cast<float4*>(&g_fac2[row][0])[t] = r;
        }
        __syncthreads();                 // row stores happen-before flag
        if (t == 0) st_release_gpu(&g_pflag[row], 1);
        return;
    }

    // ---------------- consumer ----------------
    // fold d-group partials while thread 0 polls in parallel
    if (t == 0) {
        const int4* fp = reinterpret_cast<const int4*>(g_pflag);
        for (;;) {
            int4 f0 = ld_volatile_v4(fp);
            int4 f1 = ld_volatile_v4(fp + 1);
            int4 f2 = ld_volatile_v4(fp + 2);
            if (f0.x + f0.y + f0.z + f0.w + f1.x + f1.y + f1.z + f1.w +
                f2.x + f2.y + f2.z + f2.w == C) break;
        }
        fence_acq_rel_gpu();
    }
    if (t >= 512 && t < 512 + K) {       // disjoint warps fold while warp 0 polls
        const int k = t - 512;
        float f = part[0][k];
#pragma unroll
        for (int gg = 1; gg < 8; gg++) f += part[gg][k];
        f1s[k] = f;
    }
    __syncthreads();                     // f1s ready AND fac2 visible

    // one warp per class: dot(f1s, fac2[c]) over K=512 (4 float4 per lane)
    if (w < C) {
        const float4* fa = reinterpret_cast<const float4*>(f1s);
        const float4* fb = reinterpret_cast<const float4*>(&g_fac2[w][0]);
        float p = 0.f;
#pragma unroll
        for (int j = 0; j < 4; j++) {
            const int i4 = lane + j * 32;
            float4 a = fa[i4];
            float4 b2 = fb[i4];
            p += a.x * b2.x + a.y * b2.y + a.z * b2.z + a.w * b2.w;
        }
#pragma unroll
        for (int o = 16; o > 0; o >>= 1)
            p += __shfl_xor_sync(0xffffffffu, p, o);
        if (lane == 0) hrow[w] = p;
    }
    __syncthreads();

    // parallel log_softmax in warp 0: lane c owns class c
    if (w == 0) {
        float h = (lane < C) ? hrow[lane] : -INFINITY;
        float m = h;
#pragma unroll
        for (int o = 8; o > 0; o >>= 1)
            m = fmaxf(m, __shfl_xor_sync(0xffffffffu, m, o));   // lanes 0-15 suffice
        m = __shfl_sync(0xffffffffu, m, 0);
        float e = (lane < C) ? expf(h - m) : 0.f;
        float se = e;
#pragma unroll
        for (int o = 8; o > 0; o >>= 1)
            se += __shfl_xor_sync(0xffffffffu, se, o);
        se = __shfl_sync(0xffffffffu, se, 0);
        const float lse = m + logf(se);
        if (lane < C) out[row * C + lane] = h - lse;

        // last consumer resets flags for the next graph replay
        if (lane == 0 && atomicAdd(&g_done, 1) == B - 1) {
#pragma unroll
            for (int j = 0; j < C; j++) g_pflag[j] = 0;
            g_done = 0;
        }
    }
}

extern "C" void kernel_launch(void* const* d_in, const int* in_sizes, int n_in,
                              void* d_out, int out_size) {
    const float* x  = (const float*)d_in[0];  // [32, 128]
    const float* mu = (const float*)d_in[1];  // [10, 128]
    const float* U  = (const float*)d_in[2];  // [128, 512]
    const float* V  = (const float*)d_in[3];  // [128, 512]
    float* out = (float*)d_out;               // [32, 10]

    fused_kernel<<<B + C, NT>>>(x, mu, U, V, out);
}